// round 7
// baseline (speedup 1.0000x reference)
#include <cuda_runtime.h>
#include <cuda_fp16.h>
#include <stdint.h>

#define N_NODES 100000
#define N_EDGES 3200000
#define TOT_EDGES (N_EDGES + N_NODES)
#define F_IN 256
#define HID 64
#define C_OUT 2
#define G_GRAPHS 128

#define SCAN_BLK 1024
#define SCAN_NB ((N_NODES + SCAN_BLK - 1) / SCAN_BLK)

// ---------------- scratch: __device__ globals (device-code references only) ----------------
__device__ __half g_hxh[(size_t)N_NODES * HID];   // GEMM output, pre-scaled by isq[src] (fp16)
__device__ float  g_h [(size_t)N_NODES * HID];    // agg output (fp32, read by GEMM2)
__device__ float  g_isq[N_NODES];
__device__ int    g_deg[N_NODES];
__device__ int    g_rowptr[N_NODES + 1];
__device__ int    g_cursor[N_NODES];
__device__ int    g_eidx[TOT_EDGES];
__device__ int    g_bsum[SCAN_NB + 1];
__device__ float  g_pool[G_GRAPHS * HID];
__device__ float  g_pcnt[G_GRAPHS];
__device__ int    g_is64;
__device__ __half g_W1t[64 * 256];                // W1 transposed, fp16: [n][k]
__device__ __half g_W2t[64 * 64];                 // W2 transposed, fp16: [n][k]

// ---------------- dtype detection ----------------
__global__ void k_detect(const int* __restrict__ ei_raw) {
    __shared__ int s_or[256];
    int tid = threadIdx.x;
    int acc = 0;
#pragma unroll
    for (int i = 0; i < 32; i++) {
        int w = 2 * (tid + i * 256) + 1;
        acc |= ei_raw[w];
    }
    s_or[tid] = acc;
    __syncthreads();
    for (int off = 128; off > 0; off >>= 1) {
        if (tid < off) s_or[tid] |= s_or[tid + off];
        __syncthreads();
    }
    if (tid == 0) g_is64 = (s_or[0] == 0) ? 1 : 0;
}

__device__ __forceinline__ int ld_idx(const void* p, size_t i) {
    if (g_is64) return (int)((const long long*)p)[i];
    return ((const int*)p)[i];
}

// ---------------- init ----------------
__global__ void k_init() {
    int i = blockIdx.x * blockDim.x + threadIdx.x;
    if (i < N_NODES) g_deg[i] = 1;
    if (i < G_GRAPHS * HID) g_pool[i] = 0.f;
    if (i < G_GRAPHS) g_pcnt[i] = 0.f;
}

// ---------------- W transpose + fp16 convert ----------------
__global__ void k_wt(const float* __restrict__ W1, const float* __restrict__ W2) {
    int i = blockIdx.x * blockDim.x + threadIdx.x;
    if (i < 64 * 256) {
        int n = i >> 8, k = i & 255;
        g_W1t[i] = __float2half_rn(W1[k * 64 + n]);
    }
    if (i < 64 * 64) {
        int n = i >> 6, k = i & 63;
        g_W2t[i] = __float2half_rn(W2[k * 64 + n]);
    }
}

// ---------------- degree histogram over dst ----------------
__global__ void k_deg(const void* __restrict__ ei) {
    int e = blockIdx.x * blockDim.x + threadIdx.x;
    if (e >= N_EDGES) return;
    int d = ld_idx(ei, (size_t)N_EDGES + e);
    atomicAdd(&g_deg[d], 1);
}

// ---------------- scan phase 1 ----------------
__global__ void k_scan1() {
    __shared__ int s[SCAN_BLK];
    int tid = threadIdx.x;
    int i = blockIdx.x * SCAN_BLK + tid;
    int v = (i < N_NODES) ? g_deg[i] : 0;
    s[tid] = v;
    __syncthreads();
    for (int off = 1; off < SCAN_BLK; off <<= 1) {
        int t = (tid >= off) ? s[tid - off] : 0;
        __syncthreads();
        s[tid] += t;
        __syncthreads();
    }
    if (i < N_NODES) g_cursor[i] = s[tid];
    if (tid == SCAN_BLK - 1) g_bsum[blockIdx.x] = s[tid];
}

// ---------------- scan phase 2 ----------------
__global__ void k_scan2() {
    __shared__ int s[128];
    int tid = threadIdx.x;
    int v = (tid < SCAN_NB) ? g_bsum[tid] : 0;
    s[tid] = v;
    __syncthreads();
#pragma unroll
    for (int off = 1; off < 128; off <<= 1) {
        int t = (tid >= off) ? s[tid - off] : 0;
        __syncthreads();
        s[tid] += t;
        __syncthreads();
    }
    if (tid < SCAN_NB) g_bsum[tid] = s[tid] - v;
    if (tid == 127) g_rowptr[N_NODES] = s[127];
}

// ---------------- scan phase 3 ----------------
__global__ void k_scan3() {
    int i = blockIdx.x * blockDim.x + threadIdx.x;
    if (i >= N_NODES) return;
    int incl = g_cursor[i] + g_bsum[i / SCAN_BLK];
    g_rowptr[i + 1] = incl;
    int d = g_deg[i];
    g_cursor[i] = incl - d;
    g_isq[i] = rsqrtf((float)d);
    if (i == 0) g_rowptr[0] = 0;
}

// ---------------- fill CSR ----------------
__global__ void k_fill(const void* __restrict__ ei) {
    int t = blockIdx.x * blockDim.x + threadIdx.x;
    if (t >= TOT_EDGES) return;
    int s, d;
    if (t < N_EDGES) {
        s = ld_idx(ei, t);
        d = ld_idx(ei, (size_t)N_EDGES + t);
    } else {
        s = d = t - N_EDGES;
    }
    int pos = atomicAdd(&g_cursor[d], 1);
    g_eidx[pos] = s;
}

// ---------------- tensor-core GEMM: g_hxh[N,64] = fp16(isq[n] * (X[N,K] @ W[K,64])) ----------------
// 256 threads = 8 warps; block tile M=128, N=64; mma.m16n8k16 fp16->fp32.
template <int K, int LAYER>
__global__ void k_gemm_mma(const float* __restrict__ Xin) {
    constexpr int CK = 64;
    constexpr int APAD = 72;                  // halves per sX row (36 u32 -> conflict-free)
    constexpr int WPAD = K + 8;               // halves per sWt row ((K+8)/2 % 32 == 4)
    __shared__ __half sX[128 * APAD];
    __shared__ __half sWt[64 * WPAD];

    const float*  X  = (LAYER == 1) ? Xin : (const float*)g_h;
    const __half* Wt = (LAYER == 1) ? g_W1t : g_W2t;
    int tid = threadIdx.x;
    int wid = tid >> 5, lane = tid & 31;
    int g = lane >> 2, tig = lane & 3;
    int nodeBase = blockIdx.x * 128;

    for (int i = tid; i < 64 * (K / 2); i += 256) {
        int n = i / (K / 2), kw = i % (K / 2);
        ((uint32_t*)sWt)[n * (WPAD / 2) + kw] = ((const uint32_t*)Wt)[n * (K / 2) + kw];
    }

    float acc[8][4];
#pragma unroll
    for (int nt = 0; nt < 8; nt++)
#pragma unroll
        for (int j = 0; j < 4; j++) acc[nt][j] = 0.f;

    for (int kk = 0; kk < K; kk += CK) {
        for (int i = tid; i < 128 * (CK / 2); i += 256) {
            int row = i >> 5;
            int c2 = i & 31;
            int node = nodeBase + row;
            float2 v = (node < N_NODES)
                ? *(const float2*)&X[(size_t)node * K + kk + c2 * 2]
                : make_float2(0.f, 0.f);
            ((__half2*)sX)[row * (APAD / 2) + c2] = __floats2half2_rn(v.x, v.y);
        }
        __syncthreads();

        int mrow = wid * 16;
#pragma unroll
        for (int kt = 0; kt < CK / 16; kt++) {
            int k0 = kt * 16;
            uint32_t a0 = *(const uint32_t*)&sX[(mrow + g    ) * APAD + k0     + 2 * tig];
            uint32_t a1 = *(const uint32_t*)&sX[(mrow + g + 8) * APAD + k0     + 2 * tig];
            uint32_t a2 = *(const uint32_t*)&sX[(mrow + g    ) * APAD + k0 + 8 + 2 * tig];
            uint32_t a3 = *(const uint32_t*)&sX[(mrow + g + 8) * APAD + k0 + 8 + 2 * tig];
#pragma unroll
            for (int nt = 0; nt < 8; nt++) {
                uint32_t b0 = *(const uint32_t*)&sWt[(nt * 8 + g) * WPAD + kk + k0     + 2 * tig];
                uint32_t b1 = *(const uint32_t*)&sWt[(nt * 8 + g) * WPAD + kk + k0 + 8 + 2 * tig];
                asm volatile(
                    "mma.sync.aligned.m16n8k16.row.col.f32.f16.f16.f32 "
                    "{%0,%1,%2,%3}, {%4,%5,%6,%7}, {%8,%9}, {%0,%1,%2,%3};\n"
                    : "+f"(acc[nt][0]), "+f"(acc[nt][1]), "+f"(acc[nt][2]), "+f"(acc[nt][3])
                    : "r"(a0), "r"(a1), "r"(a2), "r"(a3), "r"(b0), "r"(b1));
            }
        }
        __syncthreads();
    }

    // epilogue: pre-scale by isq[row], write fp16
    int r0 = nodeBase + wid * 16 + g;
    float s0 = (r0 < N_NODES) ? g_isq[r0] : 0.f;
    float s1 = (r0 + 8 < N_NODES) ? g_isq[r0 + 8] : 0.f;
#pragma unroll
    for (int nt = 0; nt < 8; nt++) {
        if (r0 < N_NODES)
            *(__half2*)&g_hxh[(size_t)r0 * 64 + nt * 8 + 2 * tig] =
                __floats2half2_rn(acc[nt][0] * s0, acc[nt][1] * s0);
        if (r0 + 8 < N_NODES)
            *(__half2*)&g_hxh[(size_t)(r0 + 8) * 64 + nt * 8 + 2 * tig] =
                __floats2half2_rn(acc[nt][2] * s1, acc[nt][3] * s1);
    }
}

// ---------------- pull aggregation: warp/node, staged indices, 32-deep gather MLP ----------------
template <bool FUSE_POOL>
__global__ void k_agg(const float* __restrict__ bias, const void* __restrict__ batch) {
    int gt = blockIdx.x * blockDim.x + threadIdx.x;
    int node = gt >> 5;
    int lane = gt & 31;
    if (node >= N_NODES) return;

    int r0 = g_rowptr[node];
    int r1 = g_rowptr[node + 1];
    const __half2* h2 = (const __half2*)g_hxh;

    float ax0 = 0.f, ay0 = 0.f, ax1 = 0.f, ay1 = 0.f;
    for (int base = r0; base < r1; base += 32) {
        int cnt = r1 - base;
        if (cnt > 32) cnt = 32;
        // cooperative coalesced index load (clamped for tail)
        int idx = g_eidx[base + ((lane < cnt) ? lane : 0)];
#pragma unroll
        for (int j = 0; j < 32; j++) {
            if (j >= cnt) break;                       // uniform across warp
            int s = __shfl_sync(0xffffffffu, idx, j);
            float2 v = __half22float2(h2[(size_t)s * 32 + lane]);
            if (j & 1) { ax1 += v.x; ay1 += v.y; }
            else       { ax0 += v.x; ay0 += v.y; }
        }
    }
    float ax = ax0 + ax1, ay = ay0 + ay1;

    float wd = g_isq[node];
    float ox = fmaxf(ax * wd + bias[2 * lane + 0], 0.f);
    float oy = fmaxf(ay * wd + bias[2 * lane + 1], 0.f);
    ((float2*)g_h)[(size_t)node * 32 + lane] = make_float2(ox, oy);

    if (FUSE_POOL) {
        int gph = ld_idx(batch, node);
        atomicAdd(&g_pool[gph * 64 + 2 * lane + 0], ox);
        atomicAdd(&g_pool[gph * 64 + 2 * lane + 1], oy);
        if (lane == 0) atomicAdd(&g_pcnt[gph], 1.f);
    }
}

// ---------------- final FC ----------------
__global__ void k_fc(const float* __restrict__ fcW, const float* __restrict__ fcb,
                     float* __restrict__ out) {
    int g = threadIdx.x;
    if (g >= G_GRAPHS) return;
    float cnt = g_pcnt[g];
    float inv = 1.f / fmaxf(cnt, 1.f);
    float a0 = fcb[0], a1 = fcb[1];
#pragma unroll
    for (int h = 0; h < 64; h++) {
        float p = g_pool[g * 64 + h] * inv;
        a0 += p * fcW[h * 2 + 0];
        a1 += p * fcW[h * 2 + 1];
    }
    out[g * 2 + 0] = a0;
    out[g * 2 + 1] = a1;
}

// ---------------- launch ----------------
extern "C" void kernel_launch(void* const* d_in, const int* in_sizes, int n_in,
                              void* d_out, int out_size) {
    const float* x    = (const float*)d_in[0];
    const void*  ei   = d_in[1];
    const void*  bat  = d_in[2];
    const float* W1   = (const float*)d_in[3];
    const float* b1   = (const float*)d_in[4];
    const float* W2   = (const float*)d_in[5];
    const float* b2   = (const float*)d_in[6];
    const float* fcW  = (const float*)d_in[7];
    const float* fcb  = (const float*)d_in[8];
    float* out = (float*)d_out;

    const int TPB = 256;
    int gN   = (N_NODES + TPB - 1) / TPB;
    int gE   = (N_EDGES + TPB - 1) / TPB;
    int gTOT = (TOT_EDGES + TPB - 1) / TPB;
    int gW   = (N_NODES * 32 + TPB - 1) / TPB;
    int gM   = (N_NODES + 127) / 128;

    k_detect<<<1, 256>>>((const int*)ei);
    k_init<<<gN, TPB>>>();
    k_wt<<<64, 256>>>(W1, W2);
    k_deg<<<gE, TPB>>>(ei);
    k_scan1<<<SCAN_NB, SCAN_BLK>>>();
    k_scan2<<<1, 128>>>();
    k_scan3<<<gN, TPB>>>();
    k_fill<<<gTOT, TPB>>>(ei);

    k_gemm_mma<F_IN, 1><<<gM, TPB>>>(x);              // g_hxh = fp16(isq * (x @ W1))
    k_agg<false><<<gW, TPB>>>(b1, nullptr);           // g_h = relu(isq * sum + b1)
    k_gemm_mma<HID, 2><<<gM, TPB>>>(nullptr);         // g_hxh = fp16(isq * (g_h @ W2))
    k_agg<true><<<gW, TPB>>>(b2, bat);                // g_h = relu(...) + pool

    k_fc<<<1, 128>>>(fcW, fcb, out);
}

// round 8
// speedup vs baseline: 1.1920x; 1.1920x over previous
#include <cuda_runtime.h>
#include <cuda_fp16.h>
#include <stdint.h>

#define N_NODES 100000
#define N_EDGES 3200000
#define TOT_EDGES (N_EDGES + N_NODES)
#define F_IN 256
#define HID 64
#define C_OUT 2
#define G_GRAPHS 128

#define SCAN_BLK 1024
#define SCAN_NB ((N_NODES + SCAN_BLK - 1) / SCAN_BLK)

// ---------------- scratch: __device__ globals (device-code references only) ----------------
__device__ __half g_hxh[(size_t)N_NODES * HID];   // GEMM output, pre-scaled by isq[src] (fp16)
__device__ float  g_h [(size_t)N_NODES * HID];    // agg output (fp32, read by GEMM2)
__device__ float  g_isq[N_NODES];
__device__ int    g_deg[N_NODES];
__device__ int    g_rowptr[N_NODES + 1];
__device__ int    g_cursor[N_NODES];
__device__ int    g_eidx[TOT_EDGES];
__device__ int    g_bsum[SCAN_NB + 1];
__device__ float  g_pool[G_GRAPHS * HID];
__device__ float  g_pcnt[G_GRAPHS];
__device__ int    g_is64;
__device__ __half g_W1t[64 * 256];                // W1 transposed, fp16: [n][k]
__device__ __half g_W2t[64 * 64];                 // W2 transposed, fp16: [n][k]

// ---------------- dtype detection ----------------
__global__ void k_detect(const int* __restrict__ ei_raw) {
    __shared__ int s_or[256];
    int tid = threadIdx.x;
    int acc = 0;
#pragma unroll
    for (int i = 0; i < 32; i++) {
        int w = 2 * (tid + i * 256) + 1;
        acc |= ei_raw[w];
    }
    s_or[tid] = acc;
    __syncthreads();
    for (int off = 128; off > 0; off >>= 1) {
        if (tid < off) s_or[tid] |= s_or[tid + off];
        __syncthreads();
    }
    if (tid == 0) g_is64 = (s_or[0] == 0) ? 1 : 0;
}

__device__ __forceinline__ int ld_idx(const void* p, size_t i) {
    if (g_is64) return (int)((const long long*)p)[i];
    return ((const int*)p)[i];
}

// ---------------- init ----------------
__global__ void k_init() {
    int i = blockIdx.x * blockDim.x + threadIdx.x;
    if (i < N_NODES) g_deg[i] = 1;
    if (i < G_GRAPHS * HID) g_pool[i] = 0.f;
    if (i < G_GRAPHS) g_pcnt[i] = 0.f;
}

// ---------------- W transpose + fp16 convert ----------------
__global__ void k_wt(const float* __restrict__ W1, const float* __restrict__ W2) {
    int i = blockIdx.x * blockDim.x + threadIdx.x;
    if (i < 64 * 256) {
        int n = i >> 8, k = i & 255;
        g_W1t[i] = __float2half_rn(W1[k * 64 + n]);
    }
    if (i < 64 * 64) {
        int n = i >> 6, k = i & 63;
        g_W2t[i] = __float2half_rn(W2[k * 64 + n]);
    }
}

// ---------------- degree histogram over dst ----------------
__global__ void k_deg(const void* __restrict__ ei) {
    int e = blockIdx.x * blockDim.x + threadIdx.x;
    if (e >= N_EDGES) return;
    int d = ld_idx(ei, (size_t)N_EDGES + e);
    atomicAdd(&g_deg[d], 1);
}

// ---------------- scan phase 1 ----------------
__global__ void k_scan1() {
    __shared__ int s[SCAN_BLK];
    int tid = threadIdx.x;
    int i = blockIdx.x * SCAN_BLK + tid;
    int v = (i < N_NODES) ? g_deg[i] : 0;
    s[tid] = v;
    __syncthreads();
    for (int off = 1; off < SCAN_BLK; off <<= 1) {
        int t = (tid >= off) ? s[tid - off] : 0;
        __syncthreads();
        s[tid] += t;
        __syncthreads();
    }
    if (i < N_NODES) g_cursor[i] = s[tid];
    if (tid == SCAN_BLK - 1) g_bsum[blockIdx.x] = s[tid];
}

// ---------------- scan phase 2 ----------------
__global__ void k_scan2() {
    __shared__ int s[128];
    int tid = threadIdx.x;
    int v = (tid < SCAN_NB) ? g_bsum[tid] : 0;
    s[tid] = v;
    __syncthreads();
#pragma unroll
    for (int off = 1; off < 128; off <<= 1) {
        int t = (tid >= off) ? s[tid - off] : 0;
        __syncthreads();
        s[tid] += t;
        __syncthreads();
    }
    if (tid < SCAN_NB) g_bsum[tid] = s[tid] - v;
    if (tid == 127) g_rowptr[N_NODES] = s[127];
}

// ---------------- scan phase 3 ----------------
__global__ void k_scan3() {
    int i = blockIdx.x * blockDim.x + threadIdx.x;
    if (i >= N_NODES) return;
    int incl = g_cursor[i] + g_bsum[i / SCAN_BLK];
    g_rowptr[i + 1] = incl;
    int d = g_deg[i];
    g_cursor[i] = incl - d;
    g_isq[i] = rsqrtf((float)d);
    if (i == 0) g_rowptr[0] = 0;
}

// ---------------- fill CSR ----------------
__global__ void k_fill(const void* __restrict__ ei) {
    int t = blockIdx.x * blockDim.x + threadIdx.x;
    if (t >= TOT_EDGES) return;
    int s, d;
    if (t < N_EDGES) {
        s = ld_idx(ei, t);
        d = ld_idx(ei, (size_t)N_EDGES + t);
    } else {
        s = d = t - N_EDGES;
    }
    int pos = atomicAdd(&g_cursor[d], 1);
    g_eidx[pos] = s;
}

// ---------------- tensor-core GEMM: g_hxh[N,64] = fp16(isq[n] * (X[N,K] @ W[K,64])) ----------------
template <int K, int LAYER>
__global__ void k_gemm_mma(const float* __restrict__ Xin) {
    constexpr int CK = 64;
    constexpr int APAD = 72;                  // halves per sX row (36 u32 -> conflict-free)
    constexpr int WPAD = K + 8;               // halves per sWt row ((K+8)/2 % 32 == 4)
    __shared__ __half sX[128 * APAD];
    __shared__ __half sWt[64 * WPAD];

    const float*  X  = (LAYER == 1) ? Xin : (const float*)g_h;
    const __half* Wt = (LAYER == 1) ? g_W1t : g_W2t;
    int tid = threadIdx.x;
    int wid = tid >> 5, lane = tid & 31;
    int g = lane >> 2, tig = lane & 3;
    int nodeBase = blockIdx.x * 128;

    for (int i = tid; i < 64 * (K / 2); i += 256) {
        int n = i / (K / 2), kw = i % (K / 2);
        ((uint32_t*)sWt)[n * (WPAD / 2) + kw] = ((const uint32_t*)Wt)[n * (K / 2) + kw];
    }

    float acc[8][4];
#pragma unroll
    for (int nt = 0; nt < 8; nt++)
#pragma unroll
        for (int j = 0; j < 4; j++) acc[nt][j] = 0.f;

    for (int kk = 0; kk < K; kk += CK) {
        for (int i = tid; i < 128 * (CK / 2); i += 256) {
            int row = i >> 5;
            int c2 = i & 31;
            int node = nodeBase + row;
            float2 v = (node < N_NODES)
                ? *(const float2*)&X[(size_t)node * K + kk + c2 * 2]
                : make_float2(0.f, 0.f);
            ((__half2*)sX)[row * (APAD / 2) + c2] = __floats2half2_rn(v.x, v.y);
        }
        __syncthreads();

        int mrow = wid * 16;
#pragma unroll
        for (int kt = 0; kt < CK / 16; kt++) {
            int k0 = kt * 16;
            uint32_t a0 = *(const uint32_t*)&sX[(mrow + g    ) * APAD + k0     + 2 * tig];
            uint32_t a1 = *(const uint32_t*)&sX[(mrow + g + 8) * APAD + k0     + 2 * tig];
            uint32_t a2 = *(const uint32_t*)&sX[(mrow + g    ) * APAD + k0 + 8 + 2 * tig];
            uint32_t a3 = *(const uint32_t*)&sX[(mrow + g + 8) * APAD + k0 + 8 + 2 * tig];
#pragma unroll
            for (int nt = 0; nt < 8; nt++) {
                uint32_t b0 = *(const uint32_t*)&sWt[(nt * 8 + g) * WPAD + kk + k0     + 2 * tig];
                uint32_t b1 = *(const uint32_t*)&sWt[(nt * 8 + g) * WPAD + kk + k0 + 8 + 2 * tig];
                asm volatile(
                    "mma.sync.aligned.m16n8k16.row.col.f32.f16.f16.f32 "
                    "{%0,%1,%2,%3}, {%4,%5,%6,%7}, {%8,%9}, {%0,%1,%2,%3};\n"
                    : "+f"(acc[nt][0]), "+f"(acc[nt][1]), "+f"(acc[nt][2]), "+f"(acc[nt][3])
                    : "r"(a0), "r"(a1), "r"(a2), "r"(a3), "r"(b0), "r"(b1));
            }
        }
        __syncthreads();
    }

    // epilogue: pre-scale by isq[row], write fp16
    int r0 = nodeBase + wid * 16 + g;
    float s0 = (r0 < N_NODES) ? g_isq[r0] : 0.f;
    float s1 = (r0 + 8 < N_NODES) ? g_isq[r0 + 8] : 0.f;
#pragma unroll
    for (int nt = 0; nt < 8; nt++) {
        if (r0 < N_NODES)
            *(__half2*)&g_hxh[(size_t)r0 * 64 + nt * 8 + 2 * tig] =
                __floats2half2_rn(acc[nt][0] * s0, acc[nt][1] * s0);
        if (r0 + 8 < N_NODES)
            *(__half2*)&g_hxh[(size_t)(r0 + 8) * 64 + nt * 8 + 2 * tig] =
                __floats2half2_rn(acc[nt][2] * s1, acc[nt][3] * s1);
    }
}

// ---------------- pull aggregation: warp/node, 4-way unrolled independent gathers ----------------
template <bool FUSE_POOL>
__global__ void k_agg(const float* __restrict__ bias, const void* __restrict__ batch) {
    int gt = blockIdx.x * blockDim.x + threadIdx.x;
    int node = gt >> 5;
    int lane = gt & 31;
    if (node >= N_NODES) return;

    int r0 = g_rowptr[node];
    int r1 = g_rowptr[node + 1];
    const __half2* h2 = (const __half2*)g_hxh;

    float ax0 = 0.f, ay0 = 0.f, ax1 = 0.f, ay1 = 0.f;
    float ax2 = 0.f, ay2 = 0.f, ax3 = 0.f, ay3 = 0.f;

    int e = r0;
    for (; e + 4 <= r1; e += 4) {
        int s0 = g_eidx[e    ];
        int s1 = g_eidx[e + 1];
        int s2 = g_eidx[e + 2];
        int s3 = g_eidx[e + 3];
        float2 v0 = __half22float2(h2[(size_t)s0 * 32 + lane]);
        float2 v1 = __half22float2(h2[(size_t)s1 * 32 + lane]);
        float2 v2 = __half22float2(h2[(size_t)s2 * 32 + lane]);
        float2 v3 = __half22float2(h2[(size_t)s3 * 32 + lane]);
        ax0 += v0.x; ay0 += v0.y;
        ax1 += v1.x; ay1 += v1.y;
        ax2 += v2.x; ay2 += v2.y;
        ax3 += v3.x; ay3 += v3.y;
    }
    for (; e < r1; e++) {
        int s = g_eidx[e];
        float2 v = __half22float2(h2[(size_t)s * 32 + lane]);
        ax0 += v.x; ay0 += v.y;
    }
    float ax = (ax0 + ax1) + (ax2 + ax3);
    float ay = (ay0 + ay1) + (ay2 + ay3);

    float wd = g_isq[node];
    float ox = fmaxf(ax * wd + bias[2 * lane + 0], 0.f);
    float oy = fmaxf(ay * wd + bias[2 * lane + 1], 0.f);
    ((float2*)g_h)[(size_t)node * 32 + lane] = make_float2(ox, oy);

    if (FUSE_POOL) {
        int gph = ld_idx(batch, node);
        atomicAdd(&g_pool[gph * 64 + 2 * lane + 0], ox);
        atomicAdd(&g_pool[gph * 64 + 2 * lane + 1], oy);
        if (lane == 0) atomicAdd(&g_pcnt[gph], 1.f);
    }
}

// ---------------- final FC ----------------
__global__ void k_fc(const float* __restrict__ fcW, const float* __restrict__ fcb,
                     float* __restrict__ out) {
    int g = threadIdx.x;
    if (g >= G_GRAPHS) return;
    float cnt = g_pcnt[g];
    float inv = 1.f / fmaxf(cnt, 1.f);
    float a0 = fcb[0], a1 = fcb[1];
#pragma unroll
    for (int h = 0; h < 64; h++) {
        float p = g_pool[g * 64 + h] * inv;
        a0 += p * fcW[h * 2 + 0];
        a1 += p * fcW[h * 2 + 1];
    }
    out[g * 2 + 0] = a0;
    out[g * 2 + 1] = a1;
}

// ---------------- launch ----------------
extern "C" void kernel_launch(void* const* d_in, const int* in_sizes, int n_in,
                              void* d_out, int out_size) {
    const float* x    = (const float*)d_in[0];
    const void*  ei   = d_in[1];
    const void*  bat  = d_in[2];
    const float* W1   = (const float*)d_in[3];
    const float* b1   = (const float*)d_in[4];
    const float* W2   = (const float*)d_in[5];
    const float* b2   = (const float*)d_in[6];
    const float* fcW  = (const float*)d_in[7];
    const float* fcb  = (const float*)d_in[8];
    float* out = (float*)d_out;

    const int TPB = 256;
    int gN   = (N_NODES + TPB - 1) / TPB;
    int gE   = (N_EDGES + TPB - 1) / TPB;
    int gTOT = (TOT_EDGES + TPB - 1) / TPB;
    int gW   = (N_NODES * 32 + TPB - 1) / TPB;
    int gM   = (N_NODES + 127) / 128;

    k_detect<<<1, 256>>>((const int*)ei);
    k_init<<<gN, TPB>>>();
    k_wt<<<64, 256>>>(W1, W2);
    k_deg<<<gE, TPB>>>(ei);
    k_scan1<<<SCAN_NB, SCAN_BLK>>>();
    k_scan2<<<1, 128>>>();
    k_scan3<<<gN, TPB>>>();
    k_fill<<<gTOT, TPB>>>(ei);

    k_gemm_mma<F_IN, 1><<<gM, TPB>>>(x);              // g_hxh = fp16(isq * (x @ W1))
    k_agg<false><<<gW, TPB>>>(b1, nullptr);           // g_h = relu(isq * sum + b1)
    k_gemm_mma<HID, 2><<<gM, TPB>>>(nullptr);         // g_hxh = fp16(isq * (g_h @ W2))
    k_agg<true><<<gW, TPB>>>(b2, bat);                // g_h = relu(...) + pool

    k_fc<<<1, 128>>>(fcW, fcb, out);
}

// round 9
// speedup vs baseline: 1.6185x; 1.3579x over previous
#include <cuda_runtime.h>
#include <cuda_fp16.h>
#include <stdint.h>

#define N_NODES 100000
#define N_EDGES 3200000
#define TOT_EDGES (N_EDGES + N_NODES)
#define F_IN 256
#define HID 64
#define C_OUT 2
#define G_GRAPHS 128

#define SCAN_BLK 1024
#define SCAN_NB ((N_NODES + SCAN_BLK - 1) / SCAN_BLK)

// ---------------- scratch: __device__ globals (device-code references only) ----------------
__device__ __half g_hxh[(size_t)N_NODES * HID];   // GEMM output, pre-scaled by isq[src] (fp16)
__device__ float  g_h [(size_t)N_NODES * HID];    // agg output (fp32, read by GEMM2)
__device__ float  g_isq[N_NODES];
__device__ int    g_deg[N_NODES];
__device__ int    g_rowptr[N_NODES + 1];
__device__ int    g_cursor[N_NODES];
__device__ int    g_eidx[TOT_EDGES];
__device__ int    g_bsum[SCAN_NB + 1];
__device__ float  g_pool[G_GRAPHS * HID];
__device__ float  g_pcnt[G_GRAPHS];
__device__ int    g_is64;
__device__ __half g_W1t[64 * 256];                // W1 transposed, fp16: [n][k]
__device__ __half g_W2t[64 * 64];                 // W2 transposed, fp16: [n][k]

__device__ __forceinline__ int ld_idx(const void* p, size_t i) {
    if (g_is64) return (int)((const long long*)p)[i];
    return ((const int*)p)[i];
}

// ---------------- fused setup: dtype detect + deg/pool init + W transpose ----------------
// block 0: detect; blocks 1..64: weight transpose; blocks 65..: init
__global__ void k_setup(const int* __restrict__ ei_raw,
                        const float* __restrict__ W1, const float* __restrict__ W2) {
    int b = blockIdx.x;
    int tid = threadIdx.x;
    if (b == 0) {
        __shared__ int s_or[256];
        int acc = 0;
#pragma unroll
        for (int i = 0; i < 32; i++) {
            int w = 2 * (tid + i * 256) + 1;      // odd 32-bit words; 0 iff int64 layout
            acc |= ei_raw[w];
        }
        s_or[tid] = acc;
        __syncthreads();
        for (int off = 128; off > 0; off >>= 1) {
            if (tid < off) s_or[tid] |= s_or[tid + off];
            __syncthreads();
        }
        if (tid == 0) g_is64 = (s_or[0] == 0) ? 1 : 0;
    } else if (b <= 64) {
        int i = (b - 1) * 256 + tid;              // 0..16383
        {   // W1t
            int n = i >> 8, k = i & 255;
            g_W1t[i] = __float2half_rn(W1[k * 64 + n]);
        }
        if (i < 64 * 64) {                        // W2t
            int n = i >> 6, k = i & 63;
            g_W2t[i] = __float2half_rn(W2[k * 64 + n]);
        }
    } else {
        int i = (b - 65) * 256 + tid;
        if (i < N_NODES) g_deg[i] = 1;            // self loop
        if (i < G_GRAPHS * HID) g_pool[i] = 0.f;
        if (i < G_GRAPHS) g_pcnt[i] = 0.f;
    }
}

// ---------------- degree histogram over dst ----------------
__global__ void k_deg(const void* __restrict__ ei) {
    int e = blockIdx.x * blockDim.x + threadIdx.x;
    if (e >= N_EDGES) return;
    int d = ld_idx(ei, (size_t)N_EDGES + e);
    atomicAdd(&g_deg[d], 1);
}

// ---------------- scan phase 1 ----------------
__global__ void k_scan1() {
    __shared__ int s[SCAN_BLK];
    int tid = threadIdx.x;
    int i = blockIdx.x * SCAN_BLK + tid;
    int v = (i < N_NODES) ? g_deg[i] : 0;
    s[tid] = v;
    __syncthreads();
    for (int off = 1; off < SCAN_BLK; off <<= 1) {
        int t = (tid >= off) ? s[tid - off] : 0;
        __syncthreads();
        s[tid] += t;
        __syncthreads();
    }
    if (i < N_NODES) g_cursor[i] = s[tid];
    if (tid == SCAN_BLK - 1) g_bsum[blockIdx.x] = s[tid];
}

// ---------------- scan phase 2 ----------------
__global__ void k_scan2() {
    __shared__ int s[128];
    int tid = threadIdx.x;
    int v = (tid < SCAN_NB) ? g_bsum[tid] : 0;
    s[tid] = v;
    __syncthreads();
#pragma unroll
    for (int off = 1; off < 128; off <<= 1) {
        int t = (tid >= off) ? s[tid - off] : 0;
        __syncthreads();
        s[tid] += t;
        __syncthreads();
    }
    if (tid < SCAN_NB) g_bsum[tid] = s[tid] - v;
    if (tid == 127) g_rowptr[N_NODES] = s[127];
}

// ---------------- scan phase 3 ----------------
__global__ void k_scan3() {
    int i = blockIdx.x * blockDim.x + threadIdx.x;
    if (i >= N_NODES) return;
    int incl = g_cursor[i] + g_bsum[i / SCAN_BLK];
    g_rowptr[i + 1] = incl;
    int d = g_deg[i];
    g_cursor[i] = incl - d;
    g_isq[i] = rsqrtf((float)d);
    if (i == 0) g_rowptr[0] = 0;
}

// ---------------- fill CSR ----------------
__global__ void k_fill(const void* __restrict__ ei) {
    int t = blockIdx.x * blockDim.x + threadIdx.x;
    if (t >= TOT_EDGES) return;
    int s, d;
    if (t < N_EDGES) {
        s = ld_idx(ei, t);
        d = ld_idx(ei, (size_t)N_EDGES + t);
    } else {
        s = d = t - N_EDGES;
    }
    int pos = atomicAdd(&g_cursor[d], 1);
    g_eidx[pos] = s;
}

// ---------------- tensor-core GEMM: g_hxh[N,64] = fp16(isq[n] * (X[N,K] @ W[K,64])) ----------------
template <int K, int LAYER>
__global__ void k_gemm_mma(const float* __restrict__ Xin) {
    constexpr int CK = 64;
    constexpr int APAD = 72;                  // halves per sX row (36 u32 -> conflict-free)
    constexpr int WPAD = K + 8;               // halves per sWt row ((K+8)/2 % 32 == 4)
    __shared__ __half sX[128 * APAD];
    __shared__ __half sWt[64 * WPAD];

    const float*  X  = (LAYER == 1) ? Xin : (const float*)g_h;
    const __half* Wt = (LAYER == 1) ? g_W1t : g_W2t;
    int tid = threadIdx.x;
    int wid = tid >> 5, lane = tid & 31;
    int g = lane >> 2, tig = lane & 3;
    int nodeBase = blockIdx.x * 128;

    for (int i = tid; i < 64 * (K / 2); i += 256) {
        int n = i / (K / 2), kw = i % (K / 2);
        ((uint32_t*)sWt)[n * (WPAD / 2) + kw] = ((const uint32_t*)Wt)[n * (K / 2) + kw];
    }

    float acc[8][4];
#pragma unroll
    for (int nt = 0; nt < 8; nt++)
#pragma unroll
        for (int j = 0; j < 4; j++) acc[nt][j] = 0.f;

    for (int kk = 0; kk < K; kk += CK) {
        for (int i = tid; i < 128 * (CK / 2); i += 256) {
            int row = i >> 5;
            int c2 = i & 31;
            int node = nodeBase + row;
            float2 v = (node < N_NODES)
                ? *(const float2*)&X[(size_t)node * K + kk + c2 * 2]
                : make_float2(0.f, 0.f);
            ((__half2*)sX)[row * (APAD / 2) + c2] = __floats2half2_rn(v.x, v.y);
        }
        __syncthreads();

        int mrow = wid * 16;
#pragma unroll
        for (int kt = 0; kt < CK / 16; kt++) {
            int k0 = kt * 16;
            uint32_t a0 = *(const uint32_t*)&sX[(mrow + g    ) * APAD + k0     + 2 * tig];
            uint32_t a1 = *(const uint32_t*)&sX[(mrow + g + 8) * APAD + k0     + 2 * tig];
            uint32_t a2 = *(const uint32_t*)&sX[(mrow + g    ) * APAD + k0 + 8 + 2 * tig];
            uint32_t a3 = *(const uint32_t*)&sX[(mrow + g + 8) * APAD + k0 + 8 + 2 * tig];
#pragma unroll
            for (int nt = 0; nt < 8; nt++) {
                uint32_t b0 = *(const uint32_t*)&sWt[(nt * 8 + g) * WPAD + kk + k0     + 2 * tig];
                uint32_t b1 = *(const uint32_t*)&sWt[(nt * 8 + g) * WPAD + kk + k0 + 8 + 2 * tig];
                asm volatile(
                    "mma.sync.aligned.m16n8k16.row.col.f32.f16.f16.f32 "
                    "{%0,%1,%2,%3}, {%4,%5,%6,%7}, {%8,%9}, {%0,%1,%2,%3};\n"
                    : "+f"(acc[nt][0]), "+f"(acc[nt][1]), "+f"(acc[nt][2]), "+f"(acc[nt][3])
                    : "r"(a0), "r"(a1), "r"(a2), "r"(a3), "r"(b0), "r"(b1));
            }
        }
        __syncthreads();
    }

    int r0 = nodeBase + wid * 16 + g;
    float s0 = (r0 < N_NODES) ? g_isq[r0] : 0.f;
    float s1 = (r0 + 8 < N_NODES) ? g_isq[r0 + 8] : 0.f;
#pragma unroll
    for (int nt = 0; nt < 8; nt++) {
        if (r0 < N_NODES)
            *(__half2*)&g_hxh[(size_t)r0 * 64 + nt * 8 + 2 * tig] =
                __floats2half2_rn(acc[nt][0] * s0, acc[nt][1] * s0);
        if (r0 + 8 < N_NODES)
            *(__half2*)&g_hxh[(size_t)(r0 + 8) * 64 + nt * 8 + 2 * tig] =
                __floats2half2_rn(acc[nt][2] * s1, acc[nt][3] * s1);
    }
}

// ---------------- pull aggregation: warp/node, 8-way unrolled independent gathers ----------------
// FUSE_POOL (layer 2): block-level pool reduction exploiting sorted batch.
// NOTE: grid is exactly N_NODES/8 blocks (100000 % 8 == 0), so no early returns.
template <bool FUSE_POOL>
__global__ void k_agg(const float* __restrict__ bias, const void* __restrict__ batch) {
    int gt = blockIdx.x * blockDim.x + threadIdx.x;
    int node = gt >> 5;
    int lane = gt & 31;
    int wid = threadIdx.x >> 5;

    if (!FUSE_POOL && node >= N_NODES) return;

    int r0 = g_rowptr[node];
    int r1 = g_rowptr[node + 1];
    const __half2* h2 = (const __half2*)g_hxh;

    float ax0 = 0.f, ay0 = 0.f, ax1 = 0.f, ay1 = 0.f;
    float ax2 = 0.f, ay2 = 0.f, ax3 = 0.f, ay3 = 0.f;

    int e = r0;
    for (; e + 8 <= r1; e += 8) {
        int s0 = g_eidx[e    ];
        int s1 = g_eidx[e + 1];
        int s2 = g_eidx[e + 2];
        int s3 = g_eidx[e + 3];
        int s4 = g_eidx[e + 4];
        int s5 = g_eidx[e + 5];
        int s6 = g_eidx[e + 6];
        int s7 = g_eidx[e + 7];
        float2 v0 = __half22float2(h2[(size_t)s0 * 32 + lane]);
        float2 v1 = __half22float2(h2[(size_t)s1 * 32 + lane]);
        float2 v2 = __half22float2(h2[(size_t)s2 * 32 + lane]);
        float2 v3 = __half22float2(h2[(size_t)s3 * 32 + lane]);
        float2 v4 = __half22float2(h2[(size_t)s4 * 32 + lane]);
        float2 v5 = __half22float2(h2[(size_t)s5 * 32 + lane]);
        float2 v6 = __half22float2(h2[(size_t)s6 * 32 + lane]);
        float2 v7 = __half22float2(h2[(size_t)s7 * 32 + lane]);
        ax0 += v0.x; ay0 += v0.y;
        ax1 += v1.x; ay1 += v1.y;
        ax2 += v2.x; ay2 += v2.y;
        ax3 += v3.x; ay3 += v3.y;
        ax0 += v4.x; ay0 += v4.y;
        ax1 += v5.x; ay1 += v5.y;
        ax2 += v6.x; ay2 += v6.y;
        ax3 += v7.x; ay3 += v7.y;
    }
    for (; e < r1; e++) {
        int s = g_eidx[e];
        float2 v = __half22float2(h2[(size_t)s * 32 + lane]);
        ax0 += v.x; ay0 += v.y;
    }
    float ax = (ax0 + ax1) + (ax2 + ax3);
    float ay = (ay0 + ay1) + (ay2 + ay3);

    float wd = g_isq[node];
    float ox = fmaxf(ax * wd + bias[2 * lane + 0], 0.f);
    float oy = fmaxf(ay * wd + bias[2 * lane + 1], 0.f);
    ((float2*)g_h)[(size_t)node * 32 + lane] = make_float2(ox, oy);

    if (FUSE_POOL) {
        __shared__ float s_pool[64];
        __shared__ int s_g[8];
        int gph = ld_idx(batch, node);
        if (lane == 0) s_g[wid] = gph;
        if (threadIdx.x < 64) s_pool[threadIdx.x] = 0.f;
        __syncthreads();
        if (s_g[0] == s_g[7]) {
            // whole block same graph (batch sorted): reduce in smem, 64 global REDs
            atomicAdd(&s_pool[2 * lane + 0], ox);
            atomicAdd(&s_pool[2 * lane + 1], oy);
            __syncthreads();
            if (threadIdx.x < 64) atomicAdd(&g_pool[s_g[0] * 64 + threadIdx.x], s_pool[threadIdx.x]);
            if (threadIdx.x == 0) atomicAdd(&g_pcnt[s_g[0]], 8.f);
        } else {
            atomicAdd(&g_pool[gph * 64 + 2 * lane + 0], ox);
            atomicAdd(&g_pool[gph * 64 + 2 * lane + 1], oy);
            if (lane == 0) atomicAdd(&g_pcnt[gph], 1.f);
        }
    }
}

// ---------------- final FC ----------------
__global__ void k_fc(const float* __restrict__ fcW, const float* __restrict__ fcb,
                     float* __restrict__ out) {
    int g = threadIdx.x;
    if (g >= G_GRAPHS) return;
    float cnt = g_pcnt[g];
    float inv = 1.f / fmaxf(cnt, 1.f);
    float a0 = fcb[0], a1 = fcb[1];
#pragma unroll
    for (int h = 0; h < 64; h++) {
        float p = g_pool[g * 64 + h] * inv;
        a0 += p * fcW[h * 2 + 0];
        a1 += p * fcW[h * 2 + 1];
    }
    out[g * 2 + 0] = a0;
    out[g * 2 + 1] = a1;
}

// ---------------- launch ----------------
extern "C" void kernel_launch(void* const* d_in, const int* in_sizes, int n_in,
                              void* d_out, int out_size) {
    const float* x    = (const float*)d_in[0];
    const void*  ei   = d_in[1];
    const void*  bat  = d_in[2];
    const float* W1   = (const float*)d_in[3];
    const float* b1   = (const float*)d_in[4];
    const float* W2   = (const float*)d_in[5];
    const float* b2   = (const float*)d_in[6];
    const float* fcW  = (const float*)d_in[7];
    const float* fcb  = (const float*)d_in[8];
    float* out = (float*)d_out;

    const int TPB = 256;
    int gN   = (N_NODES + TPB - 1) / TPB;            // 391
    int gE   = (N_EDGES + TPB - 1) / TPB;
    int gTOT = (TOT_EDGES + TPB - 1) / TPB;
    int gW   = (N_NODES * 32) / TPB;                 // 12500 exactly
    int gM   = (N_NODES + 127) / 128;

    k_setup<<<1 + 64 + gN, TPB>>>((const int*)ei, W1, W2);
    k_deg<<<gE, TPB>>>(ei);
    k_scan1<<<SCAN_NB, SCAN_BLK>>>();
    k_scan2<<<1, 128>>>();
    k_scan3<<<gN, TPB>>>();
    k_fill<<<gTOT, TPB>>>(ei);

    k_gemm_mma<F_IN, 1><<<gM, TPB>>>(x);              // g_hxh = fp16(isq * (x @ W1))
    k_agg<false><<<gW, TPB>>>(b1, nullptr);           // g_h = relu(isq * sum + b1)
    k_gemm_mma<HID, 2><<<gM, TPB>>>(nullptr);         // g_hxh = fp16(isq * (g_h @ W2))
    k_agg<true><<<gW, TPB>>>(b2, bat);                // g_h = relu(...) + block-pooled

    k_fc<<<1, 128>>>(fcW, fcb, out);
}